// round 1
// baseline (speedup 1.0000x reference)
#include <cuda_runtime.h>
#include <cstdint>

// Problem geometry (fixed for this dataset instance)
#define CC   3
#define HH   496
#define WW   432
#define HWSZ (HH * WW)        // 214272
#define MAXB 8
#define NBUCK 8192            // float_bits >> 17, scores in (0,1) -> max 8127
#define CAP  4096             // candidate buffer per batch (expect ~600)

// Scratch (no allocations allowed -> __device__ globals)
__device__ float              g_scores[MAXB * CC * HWSZ];   // ~20.6 MB
__device__ int                g_hist[MAXB * NBUCK];
__device__ int                g_thresh[MAXB];
__device__ int                g_count[MAXB];
__device__ unsigned long long g_cand[MAXB * CAP];

__device__ __forceinline__ float sigclip(float x) {
    float s = 1.0f / (1.0f + __expf(-x));
    return fminf(fmaxf(s, 1.0e-4f), 1.0f - 1.0e-4f);
}

// ---------------------------------------------------------------------------
// K0: zero histograms + counters
// ---------------------------------------------------------------------------
__global__ void k0_zero() {
    int i = blockIdx.x * blockDim.x + threadIdx.x;
    if (i < MAXB * NBUCK) g_hist[i] = 0;
    if (i < MAXB)         g_count[i] = 0;
}

// ---------------------------------------------------------------------------
// K1: sigmoid + 3x3 NMS (raw-domain compare; sigmoid is monotone) + histogram
// ---------------------------------------------------------------------------
__global__ void k1_score(const float* __restrict__ hm, int B) {
    int i = blockIdx.x * blockDim.x + threadIdx.x;
    int npix = B * CC * HWSZ;
    if (i >= npix) return;

    int w  = i % WW;
    int t  = i / WW;
    int h  = t % HH;
    int bc = t / HH;                  // b*CC + c

    float v = hm[i];
    bool keep = true;
    #pragma unroll
    for (int dh = -1; dh <= 1; dh++) {
        int hh = h + dh;
        if (hh < 0 || hh >= HH) continue;
        #pragma unroll
        for (int dw = -1; dw <= 1; dw++) {
            if (dh == 0 && dw == 0) continue;
            int ww = w + dw;
            if (ww < 0 || ww >= WW) continue;
            float nv = hm[i + dh * WW + dw];
            if (nv > v) keep = false;
        }
    }

    float s = 0.0f;
    if (keep) s = sigclip(v);
    g_scores[i] = s;

    if (s > 0.0f) {
        int b = bc / CC;
        unsigned int bits = __float_as_uint(s);
        int bucket = (int)(bits >> 17);
        atomicAdd(&g_hist[b * NBUCK + bucket], 1);
    }
}

// ---------------------------------------------------------------------------
// K2: per-batch threshold bucket (smallest T s.t. suffix count >= K)
// ---------------------------------------------------------------------------
__global__ void k2_thresh(int K) {
    int b = blockIdx.x;
    __shared__ int chunk[256];
    int t = threadIdx.x;                 // 256 threads, 32 buckets each
    int s = 0;
    const int* hist = &g_hist[b * NBUCK];
    #pragma unroll 4
    for (int j = 0; j < 32; j++) s += hist[t * 32 + j];
    chunk[t] = s;
    __syncthreads();

    if (t == 0) {
        int cum = 0;
        int T = 0;
        bool done = false;
        for (int cix = 255; cix >= 0 && !done; cix--) {
            if (cum + chunk[cix] >= K) {
                for (int j = 31; j >= 0; j--) {
                    cum += hist[cix * 32 + j];
                    if (cum >= K) { T = cix * 32 + j; done = true; break; }
                }
            } else {
                cum += chunk[cix];
            }
        }
        g_thresh[b] = T;   // collect criterion: bucket >= T  (0 if < K total)
    }
}

// ---------------------------------------------------------------------------
// K3: collect candidates >= threshold bucket into per-batch arrays
// ---------------------------------------------------------------------------
__global__ void k3_collect(int B) {
    int i = blockIdx.x * blockDim.x + threadIdx.x;
    int npix = B * CC * HWSZ;
    if (i >= npix) return;

    float s = g_scores[i];
    if (s <= 0.0f) return;
    int b = i / (CC * HWSZ);
    unsigned int bits = __float_as_uint(s);
    int bucket = (int)(bits >> 17);
    if (bucket < g_thresh[b]) return;

    int pos = atomicAdd(&g_count[b], 1);
    if (pos < CAP) {
        unsigned int idx = (unsigned int)(i - b * CC * HWSZ);   // c*HW + hw
        // key: score desc, then idx asc on a descending sort
        unsigned long long key =
            ((unsigned long long)bits << 32) | (unsigned long long)(~idx);
        g_cand[b * CAP + pos] = key;
    }
}

// ---------------------------------------------------------------------------
// K4: per-batch bitonic sort (desc) + gather + write detections
// ---------------------------------------------------------------------------
__global__ __launch_bounds__(512)
void k4_sort_gather(const float* __restrict__ cen_offset,
                    const float* __restrict__ direction,
                    const float* __restrict__ z_coor,
                    const float* __restrict__ dimf,
                    float* __restrict__ out,
                    int K) {
    __shared__ unsigned long long keys[CAP];   // 32 KB
    int b   = blockIdx.x;
    int tid = threadIdx.x;
    int n   = g_count[b];
    if (n > CAP) n = CAP;

    for (int i = tid; i < CAP; i += blockDim.x)
        keys[i] = (i < n) ? g_cand[b * CAP + i] : 0ULL;
    __syncthreads();

    // Bitonic sort, descending
    for (int k2 = 2; k2 <= CAP; k2 <<= 1) {
        for (int j = k2 >> 1; j > 0; j >>= 1) {
            for (int i = tid; i < CAP; i += blockDim.x) {
                int ixj = i ^ j;
                if (ixj > i) {
                    unsigned long long a = keys[i];
                    unsigned long long c = keys[ixj];
                    bool up = ((i & k2) == 0);     // up-part should be DESC
                    if (up ? (a < c) : (a > c)) {
                        keys[i]   = c;
                        keys[ixj] = a;
                    }
                }
            }
            __syncthreads();
        }
    }

    for (int k = tid; k < K; k += blockDim.x) {
        float* o = out + ((size_t)b * K + k) * 10;
        unsigned long long key = keys[k];
        if (key == 0ULL) {
            #pragma unroll
            for (int q = 0; q < 10; q++) o[q] = 0.0f;
            continue;
        }
        float score = __uint_as_float((unsigned int)(key >> 32));
        unsigned int idx = ~((unsigned int)key);       // c*HW + hw
        int c  = (int)(idx / HWSZ);
        int hw = (int)(idx - (unsigned int)c * HWSZ);
        int r  = hw / WW;
        int w  = hw - r * WW;

        const float* off = cen_offset + (size_t)b * 2 * HWSZ;
        const float* dir = direction  + (size_t)b * 2 * HWSZ;
        const float* zc  = z_coor     + (size_t)b * 1 * HWSZ;
        const float* dm  = dimf       + (size_t)b * 3 * HWSZ;

        float off0 = sigclip(off[hw]);
        float off1 = sigclip(off[HWSZ + hw]);

        o[0] = score;
        o[1] = (float)w + off0;
        o[2] = (float)r + off1;
        o[3] = zc[hw];
        o[4] = dm[hw];
        o[5] = dm[HWSZ + hw];
        o[6] = dm[2 * HWSZ + hw];
        o[7] = dir[hw];
        o[8] = dir[HWSZ + hw];
        o[9] = (float)c;
    }
}

// ---------------------------------------------------------------------------
// Host launcher
// ---------------------------------------------------------------------------
extern "C" void kernel_launch(void* const* d_in, const int* in_sizes, int n_in,
                              void* d_out, int out_size) {
    const float* hm   = (const float*)d_in[0];
    const float* off  = (const float*)d_in[1];
    const float* dir  = (const float*)d_in[2];
    const float* zc   = (const float*)d_in[3];
    const float* dm   = (const float*)d_in[4];
    float* out = (float*)d_out;

    int B = in_sizes[0] / (CC * HWSZ);
    if (B < 1) B = 1;
    if (B > MAXB) B = MAXB;
    int K = out_size / (B * 10);
    if (K < 1) K = 1;

    int npix = B * CC * HWSZ;
    int nz = MAXB * NBUCK;

    k0_zero<<<(nz + 255) / 256, 256>>>();
    k1_score<<<(npix + 255) / 256, 256>>>(hm, B);
    k2_thresh<<<B, 256>>>(K);
    k3_collect<<<(npix + 255) / 256, 256>>>(B);
    k4_sort_gather<<<B, 512>>>(off, dir, zc, dm, out, K);
}

// round 2
// speedup vs baseline: 1.0078x; 1.0078x over previous
#include <cuda_runtime.h>
#include <cstdint>

// Problem geometry (fixed for this dataset instance)
#define CC   3
#define HH   496
#define WW   432
#define HWSZ (HH * WW)        // 214272
#define MAXB 8
#define NBUCK 8192            // float_bits >> 17, scores in (0,1) -> max 8127
#define CAP  4096             // candidate buffer per batch (expect ~600)

// Scratch (no allocations allowed -> __device__ globals)
__device__ float              g_scores[MAXB * CC * HWSZ];   // ~20.6 MB
__device__ int                g_hist[MAXB * NBUCK];
__device__ int                g_thresh[MAXB];
__device__ int                g_count[MAXB];
__device__ unsigned long long g_cand[MAXB * CAP];

__device__ __forceinline__ float sigclip(float x) {
    float s = 1.0f / (1.0f + __expf(-x));
    return fminf(fmaxf(s, 1.0e-4f), 1.0f - 1.0e-4f);
}

// ---------------------------------------------------------------------------
// K0: zero histograms + counters
// ---------------------------------------------------------------------------
__global__ void k0_zero() {
    int i = blockIdx.x * blockDim.x + threadIdx.x;
    if (i < MAXB * NBUCK) g_hist[i] = 0;
    if (i < MAXB)         g_count[i] = 0;
}

// ---------------------------------------------------------------------------
// K1: sigmoid + 3x3 NMS (raw-domain compare; sigmoid is monotone) + histogram
// ---------------------------------------------------------------------------
__global__ void k1_score(const float* __restrict__ hm, int B) {
    int i = blockIdx.x * blockDim.x + threadIdx.x;
    int npix = B * CC * HWSZ;
    if (i >= npix) return;

    int w  = i % WW;
    int t  = i / WW;
    int h  = t % HH;
    int bc = t / HH;                  // b*CC + c

    float v = hm[i];
    bool keep = true;
    #pragma unroll
    for (int dh = -1; dh <= 1; dh++) {
        int hh = h + dh;
        if (hh < 0 || hh >= HH) continue;
        #pragma unroll
        for (int dw = -1; dw <= 1; dw++) {
            if (dh == 0 && dw == 0) continue;
            int ww = w + dw;
            if (ww < 0 || ww >= WW) continue;
            float nv = hm[i + dh * WW + dw];
            if (nv > v) keep = false;
        }
    }

    float s = 0.0f;
    if (keep) s = sigclip(v);
    g_scores[i] = s;

    if (s > 0.0f) {
        int b = bc / CC;
        unsigned int bits = __float_as_uint(s);
        int bucket = (int)(bits >> 17);
        atomicAdd(&g_hist[b * NBUCK + bucket], 1);
    }
}

// ---------------------------------------------------------------------------
// K2: per-batch threshold bucket (smallest T s.t. suffix count >= K)
// ---------------------------------------------------------------------------
__global__ void k2_thresh(int K) {
    int b = blockIdx.x;
    __shared__ int chunk[256];
    int t = threadIdx.x;                 // 256 threads, 32 buckets each
    int s = 0;
    const int* hist = &g_hist[b * NBUCK];
    #pragma unroll 4
    for (int j = 0; j < 32; j++) s += hist[t * 32 + j];
    chunk[t] = s;
    __syncthreads();

    if (t == 0) {
        int cum = 0;
        int T = 0;
        bool done = false;
        for (int cix = 255; cix >= 0 && !done; cix--) {
            if (cum + chunk[cix] >= K) {
                for (int j = 31; j >= 0; j--) {
                    cum += hist[cix * 32 + j];
                    if (cum >= K) { T = cix * 32 + j; done = true; break; }
                }
            } else {
                cum += chunk[cix];
            }
        }
        g_thresh[b] = T;   // collect criterion: bucket >= T  (0 if < K total)
    }
}

// ---------------------------------------------------------------------------
// K3: collect candidates >= threshold bucket into per-batch arrays
// ---------------------------------------------------------------------------
__global__ void k3_collect(int B) {
    int i = blockIdx.x * blockDim.x + threadIdx.x;
    int npix = B * CC * HWSZ;
    if (i >= npix) return;

    float s = g_scores[i];
    if (s <= 0.0f) return;
    int b = i / (CC * HWSZ);
    unsigned int bits = __float_as_uint(s);
    int bucket = (int)(bits >> 17);
    if (bucket < g_thresh[b]) return;

    int pos = atomicAdd(&g_count[b], 1);
    if (pos < CAP) {
        unsigned int idx = (unsigned int)(i - b * CC * HWSZ);   // c*HW + hw
        // key: score desc, then idx asc on a descending sort
        unsigned long long key =
            ((unsigned long long)bits << 32) | (unsigned long long)(~idx);
        g_cand[b * CAP + pos] = key;
    }
}

// ---------------------------------------------------------------------------
// K4: per-batch bitonic sort (desc) + gather + write detections
// ---------------------------------------------------------------------------
__global__ __launch_bounds__(512)
void k4_sort_gather(const float* __restrict__ cen_offset,
                    const float* __restrict__ direction,
                    const float* __restrict__ z_coor,
                    const float* __restrict__ dimf,
                    float* __restrict__ out,
                    int K) {
    __shared__ unsigned long long keys[CAP];   // 32 KB
    int b   = blockIdx.x;
    int tid = threadIdx.x;
    int n   = g_count[b];
    if (n > CAP) n = CAP;

    for (int i = tid; i < CAP; i += blockDim.x)
        keys[i] = (i < n) ? g_cand[b * CAP + i] : 0ULL;
    __syncthreads();

    // Bitonic sort, descending
    for (int k2 = 2; k2 <= CAP; k2 <<= 1) {
        for (int j = k2 >> 1; j > 0; j >>= 1) {
            for (int i = tid; i < CAP; i += blockDim.x) {
                int ixj = i ^ j;
                if (ixj > i) {
                    unsigned long long a = keys[i];
                    unsigned long long c = keys[ixj];
                    bool up = ((i & k2) == 0);     // up-part should be DESC
                    if (up ? (a < c) : (a > c)) {
                        keys[i]   = c;
                        keys[ixj] = a;
                    }
                }
            }
            __syncthreads();
        }
    }

    for (int k = tid; k < K; k += blockDim.x) {
        float* o = out + ((size_t)b * K + k) * 10;
        unsigned long long key = keys[k];
        if (key == 0ULL) {
            #pragma unroll
            for (int q = 0; q < 10; q++) o[q] = 0.0f;
            continue;
        }
        float score = __uint_as_float((unsigned int)(key >> 32));
        unsigned int idx = ~((unsigned int)key);       // c*HW + hw
        int c  = (int)(idx / HWSZ);
        int hw = (int)(idx - (unsigned int)c * HWSZ);
        int r  = hw / WW;
        int w  = hw - r * WW;

        const float* off = cen_offset + (size_t)b * 2 * HWSZ;
        const float* dir = direction  + (size_t)b * 2 * HWSZ;
        const float* zc  = z_coor     + (size_t)b * 1 * HWSZ;
        const float* dm  = dimf       + (size_t)b * 3 * HWSZ;

        float off0 = sigclip(off[hw]);
        float off1 = sigclip(off[HWSZ + hw]);

        o[0] = score;
        o[1] = (float)w + off0;
        o[2] = (float)r + off1;
        o[3] = zc[hw];
        o[4] = dm[hw];
        o[5] = dm[HWSZ + hw];
        o[6] = dm[2 * HWSZ + hw];
        o[7] = dir[hw];
        o[8] = dir[HWSZ + hw];
        o[9] = (float)c;
    }
}

// ---------------------------------------------------------------------------
// Host launcher
// ---------------------------------------------------------------------------
extern "C" void kernel_launch(void* const* d_in, const int* in_sizes, int n_in,
                              void* d_out, int out_size) {
    const float* hm   = (const float*)d_in[0];
    const float* off  = (const float*)d_in[1];
    const float* dir  = (const float*)d_in[2];
    const float* zc   = (const float*)d_in[3];
    const float* dm   = (const float*)d_in[4];
    float* out = (float*)d_out;

    int B = in_sizes[0] / (CC * HWSZ);
    if (B < 1) B = 1;
    if (B > MAXB) B = MAXB;
    int K = out_size / (B * 10);
    if (K < 1) K = 1;

    int npix = B * CC * HWSZ;
    int nz = MAXB * NBUCK;

    k0_zero<<<(nz + 255) / 256, 256>>>();
    k1_score<<<(npix + 255) / 256, 256>>>(hm, B);
    k2_thresh<<<B, 256>>>(K);
    k3_collect<<<(npix + 255) / 256, 256>>>(B);
    k4_sort_gather<<<B, 512>>>(off, dir, zc, dm, out, K);
}

// round 3
// speedup vs baseline: 2.0156x; 2.0000x over previous
#include <cuda_runtime.h>
#include <cstdint>

// Problem geometry (fixed for this dataset instance)
#define CC    3
#define HH    496
#define WW    432
#define HWSZ  (HH * WW)            // 214272
#define PLANE (CC * HWSZ)          // 642816
#define MAXB  8
#define NBUCK 8192                 // ordered_bits >> 19
#define CAP   4096                 // candidate buffer per batch (expect ~700)
#define SURVCAP 131072             // survivor buffer per batch (expect ~72K)
#define K1_BLOCKS ((PLANE + 1023) / 1024)   // 628 blocks of 256 thr x 4 px

// Scratch (no allocations allowed -> __device__ globals)
__device__ unsigned long long g_surv[MAXB * SURVCAP];   // 8 MB
__device__ int                g_hist[MAXB * NBUCK];
__device__ int                g_scount[MAXB];
__device__ int                g_thresh[MAXB];
__device__ int                g_count[MAXB];
__device__ unsigned long long g_cand[MAXB * CAP];

__device__ __forceinline__ float sigclip(float x) {
    float s = 1.0f / (1.0f + __expf(-x));
    return fminf(fmaxf(s, 1.0e-4f), 1.0f - 1.0e-4f);
}

// total-order key for floats (monotone map to uint32, ascending)
__device__ __forceinline__ unsigned int ordkey(float v) {
    unsigned int bits = __float_as_uint(v);
    return bits ^ ((unsigned int)((int)bits >> 31) | 0x80000000u);
}

// ---------------------------------------------------------------------------
// K0: zero histograms + counters
// ---------------------------------------------------------------------------
__global__ void k0_zero() {
    int i = blockIdx.x * blockDim.x + threadIdx.x;
    if (i < MAXB * NBUCK) g_hist[i] = 0;
    if (i < MAXB) { g_count[i] = 0; g_scount[i] = 0; }
}

// ---------------------------------------------------------------------------
// K1: raw-domain 3x3 NMS (sigmoid is monotone) -> survivor list + histogram
//     4 pixels per thread (float4 aligned; WW and HWSZ are multiples of 4,
//     so a 4-group never crosses a row or channel).
// ---------------------------------------------------------------------------
__global__ __launch_bounds__(256)
void k1_nms(const float* __restrict__ hm) {
    int b    = blockIdx.y;
    int base = blockIdx.x * 1024 + threadIdx.x * 4;   // within plane

    __shared__ int s_cnt, s_base;
    if (threadIdx.x == 0) s_cnt = 0;
    __syncthreads();

    unsigned long long mykeys[4];
    int myn = 0;

    if (base < PLANE) {
        const float* plane = hm + (size_t)b * PLANE;
        int hw = base % HWSZ;
        int h  = hw / WW;
        int w  = hw % WW;
        const float* p = plane + base;
        const float NEG = -3.4e38f;

        float rc[6], ru[6], rd[6];
        float4 c4 = *reinterpret_cast<const float4*>(p);
        rc[0] = (w > 0)        ? p[-1] : NEG;
        rc[1] = c4.x; rc[2] = c4.y; rc[3] = c4.z; rc[4] = c4.w;
        rc[5] = (w + 4 < WW)   ? p[4]  : NEG;

        if (h > 0) {
            const float* q = p - WW;
            float4 u4 = *reinterpret_cast<const float4*>(q);
            ru[0] = (w > 0) ? q[-1] : NEG;
            ru[1] = u4.x; ru[2] = u4.y; ru[3] = u4.z; ru[4] = u4.w;
            ru[5] = (w + 4 < WW) ? q[4] : NEG;
        } else {
            #pragma unroll
            for (int j = 0; j < 6; j++) ru[j] = NEG;
        }
        if (h + 1 < HH) {
            const float* q = p + WW;
            float4 d4 = *reinterpret_cast<const float4*>(q);
            rd[0] = (w > 0) ? q[-1] : NEG;
            rd[1] = d4.x; rd[2] = d4.y; rd[3] = d4.z; rd[4] = d4.w;
            rd[5] = (w + 4 < WW) ? q[4] : NEG;
        } else {
            #pragma unroll
            for (int j = 0; j < 6; j++) rd[j] = NEG;
        }

        #pragma unroll
        for (int j = 0; j < 4; j++) {
            float v = rc[j + 1];
            float m = fmaxf(rc[j], rc[j + 2]);                          // same row, excl center
            m = fmaxf(m, fmaxf(fmaxf(ru[j], ru[j + 1]), ru[j + 2]));    // row above
            m = fmaxf(m, fmaxf(fmaxf(rd[j], rd[j + 1]), rd[j + 2]));    // row below
            if (v >= m) {                                               // keep iff no neighbor > v
                unsigned int ord = ordkey(v);
                atomicAdd(&g_hist[b * NBUCK + (ord >> 19)], 1);
                unsigned int idx = (unsigned int)(base + j);            // c*HW + hw
                mykeys[myn++] = ((unsigned long long)ord << 32) |
                                (unsigned long long)(~idx);
            }
        }
    }

    int local = 0;
    if (myn) local = atomicAdd(&s_cnt, myn);
    __syncthreads();
    if (threadIdx.x == 0) s_base = atomicAdd(&g_scount[b], s_cnt);
    __syncthreads();
    if (myn) {
        int pos = s_base + local;
        for (int j = 0; j < myn; j++) {
            int pp = pos + j;
            if (pp < SURVCAP) g_surv[b * SURVCAP + pp] = mykeys[j];
        }
    }
}

// ---------------------------------------------------------------------------
// K2: per-batch threshold bucket (smallest T s.t. suffix count >= K)
// ---------------------------------------------------------------------------
__global__ void k2_thresh(int K) {
    int b = blockIdx.x;
    __shared__ int chunk[256];
    int t = threadIdx.x;                 // 256 threads, 32 buckets each
    int s = 0;
    const int* hist = &g_hist[b * NBUCK];
    #pragma unroll 4
    for (int j = 0; j < 32; j++) s += hist[t * 32 + j];
    chunk[t] = s;
    __syncthreads();

    if (t == 0) {
        int cum = 0;
        int T = 0;
        bool done = false;
        for (int cix = 255; cix >= 0 && !done; cix--) {
            if (cum + chunk[cix] >= K) {
                for (int j = 31; j >= 0; j--) {
                    cum += hist[cix * 32 + j];
                    if (cum >= K) { T = cix * 32 + j; done = true; break; }
                }
            } else {
                cum += chunk[cix];
            }
        }
        g_thresh[b] = T;   // collect criterion: bucket >= T  (0 if < K total)
    }
}

// ---------------------------------------------------------------------------
// K3: filter survivor list by threshold bucket into candidate arrays
// ---------------------------------------------------------------------------
__global__ void k3_collect() {
    int b = blockIdx.y;
    int i = blockIdx.x * blockDim.x + threadIdx.x;
    int n = g_scount[b];
    if (n > SURVCAP) n = SURVCAP;
    if (i >= n) return;

    unsigned long long key = g_surv[b * SURVCAP + i];
    int bucket = (int)(key >> (32 + 19));
    if (bucket < g_thresh[b]) return;

    int pos = atomicAdd(&g_count[b], 1);
    if (pos < CAP) g_cand[b * CAP + pos] = key;
}

// ---------------------------------------------------------------------------
// K4: per-batch bitonic sort (desc, only next_pow2(n) elems) + gather + write
// ---------------------------------------------------------------------------
__global__ __launch_bounds__(1024)
void k4_sort_gather(const float* __restrict__ cen_offset,
                    const float* __restrict__ direction,
                    const float* __restrict__ z_coor,
                    const float* __restrict__ dimf,
                    float* __restrict__ out,
                    int K) {
    __shared__ unsigned long long keys[CAP];   // 32 KB
    int b   = blockIdx.x;
    int tid = threadIdx.x;
    int n   = g_count[b];
    if (n > CAP) n = CAP;
    int m = 512;
    while (m < n) m <<= 1;                     // sort size, <= CAP

    for (int i = tid; i < m; i += blockDim.x)
        keys[i] = (i < n) ? g_cand[b * CAP + i] : 0ULL;
    __syncthreads();

    // Bitonic sort, descending
    for (int k2 = 2; k2 <= m; k2 <<= 1) {
        for (int j = k2 >> 1; j > 0; j >>= 1) {
            for (int i = tid; i < m; i += blockDim.x) {
                int ixj = i ^ j;
                if (ixj > i) {
                    unsigned long long a = keys[i];
                    unsigned long long c = keys[ixj];
                    bool up = ((i & k2) == 0);
                    if (up ? (a < c) : (a > c)) {
                        keys[i]   = c;
                        keys[ixj] = a;
                    }
                }
            }
            __syncthreads();
        }
    }

    for (int k = tid; k < K; k += blockDim.x) {
        float* o = out + ((size_t)b * K + k) * 10;
        unsigned long long key = keys[k];
        if (key == 0ULL) {
            #pragma unroll
            for (int q = 0; q < 10; q++) o[q] = 0.0f;
            continue;
        }
        unsigned int ord  = (unsigned int)(key >> 32);
        unsigned int bits = (ord & 0x80000000u) ? (ord ^ 0x80000000u) : ~ord;
        float score = sigclip(__uint_as_float(bits));
        unsigned int idx = ~((unsigned int)key);       // c*HW + hw
        int c  = (int)(idx / HWSZ);
        int hw = (int)(idx - (unsigned int)c * HWSZ);
        int r  = hw / WW;
        int w  = hw - r * WW;

        const float* off = cen_offset + (size_t)b * 2 * HWSZ;
        const float* dir = direction  + (size_t)b * 2 * HWSZ;
        const float* zc  = z_coor     + (size_t)b * 1 * HWSZ;
        const float* dm  = dimf       + (size_t)b * 3 * HWSZ;

        o[0] = score;
        o[1] = (float)w + sigclip(off[hw]);
        o[2] = (float)r + sigclip(off[HWSZ + hw]);
        o[3] = zc[hw];
        o[4] = dm[hw];
        o[5] = dm[HWSZ + hw];
        o[6] = dm[2 * HWSZ + hw];
        o[7] = dir[hw];
        o[8] = dir[HWSZ + hw];
        o[9] = (float)c;
    }
}

// ---------------------------------------------------------------------------
// Host launcher
// ---------------------------------------------------------------------------
extern "C" void kernel_launch(void* const* d_in, const int* in_sizes, int n_in,
                              void* d_out, int out_size) {
    const float* hm   = (const float*)d_in[0];
    const float* off  = (const float*)d_in[1];
    const float* dir  = (const float*)d_in[2];
    const float* zc   = (const float*)d_in[3];
    const float* dm   = (const float*)d_in[4];
    float* out = (float*)d_out;

    int B = in_sizes[0] / PLANE;
    if (B < 1) B = 1;
    if (B > MAXB) B = MAXB;
    int K = out_size / (B * 10);
    if (K < 1) K = 1;

    int nz = MAXB * NBUCK;

    k0_zero<<<(nz + 255) / 256, 256>>>();
    k1_nms<<<dim3(K1_BLOCKS, B), 256>>>(hm);
    k2_thresh<<<B, 256>>>(K);
    k3_collect<<<dim3(SURVCAP / 256, B), 256>>>();
    k4_sort_gather<<<B, 1024>>>(off, dir, zc, dm, out, K);
}

// round 4
// speedup vs baseline: 2.6796x; 1.3294x over previous
#include <cuda_runtime.h>
#include <cstdint>

// Problem geometry (fixed for this dataset instance)
#define CC    3
#define HH    496
#define WW    432
#define HWSZ  (HH * WW)            // 214272
#define PLANE (CC * HWSZ)          // 642816
#define MAXB  8
#define NBUCK 8192                 // ordered_bits >> 19
#define NSH   4                    // histogram shards (contention relief)
#define CAP   4096                 // candidate buffer per batch
#define SURVCAP 131072             // survivor buffer per batch (expect ~72K)
#define K1_BLOCKS ((PLANE + 1023) / 1024)   // 628 blocks of 256 thr x 4 px

// One contiguous zeroed scratch region: hist[b][sh][bucket] then counters.
#define HIST_INTS   (MAXB * NSH * NBUCK)       // 262144 ints = 1 MB
#define SCOUNT_OFF  (HIST_INTS)                // 8 ints
#define COUNT_OFF   (HIST_INTS + MAXB)         // 8 ints
#define ZERO_INTS   (HIST_INTS + 2 * MAXB)

__device__ int                g_zero[ZERO_INTS];
__device__ int                g_thresh[MAXB];
__device__ unsigned long long g_surv[MAXB * SURVCAP];   // 8 MB
__device__ unsigned long long g_cand[MAXB * CAP];

__device__ __forceinline__ float sigclip(float x) {
    float s = 1.0f / (1.0f + __expf(-x));
    return fminf(fmaxf(s, 1.0e-4f), 1.0f - 1.0e-4f);
}

// total-order key for floats (monotone map to uint32, ascending)
__device__ __forceinline__ unsigned int ordkey(float v) {
    unsigned int bits = __float_as_uint(v);
    return bits ^ ((unsigned int)((int)bits >> 31) | 0x80000000u);
}

// ---------------------------------------------------------------------------
// K1: raw-domain 3x3 NMS (sigmoid is monotone) -> survivor list + sharded hist
// ---------------------------------------------------------------------------
__global__ __launch_bounds__(256)
void k1_nms(const float* __restrict__ hm) {
    int b    = blockIdx.y;
    int base = blockIdx.x * 1024 + threadIdx.x * 4;   // within plane
    int sh   = threadIdx.x & (NSH - 1);

    __shared__ int s_cnt, s_base;
    if (threadIdx.x == 0) s_cnt = 0;
    __syncthreads();

    unsigned long long mykeys[4];
    int myn = 0;

    if (base < PLANE) {
        const float* plane = hm + (size_t)b * PLANE;
        int hw = base % HWSZ;
        int h  = hw / WW;
        int w  = hw % WW;
        const float* p = plane + base;
        const float NEG = -3.4e38f;

        float rc[6], ru[6], rd[6];
        float4 c4 = *reinterpret_cast<const float4*>(p);
        rc[0] = (w > 0)        ? p[-1] : NEG;
        rc[1] = c4.x; rc[2] = c4.y; rc[3] = c4.z; rc[4] = c4.w;
        rc[5] = (w + 4 < WW)   ? p[4]  : NEG;

        if (h > 0) {
            const float* q = p - WW;
            float4 u4 = *reinterpret_cast<const float4*>(q);
            ru[0] = (w > 0) ? q[-1] : NEG;
            ru[1] = u4.x; ru[2] = u4.y; ru[3] = u4.z; ru[4] = u4.w;
            ru[5] = (w + 4 < WW) ? q[4] : NEG;
        } else {
            #pragma unroll
            for (int j = 0; j < 6; j++) ru[j] = NEG;
        }
        if (h + 1 < HH) {
            const float* q = p + WW;
            float4 d4 = *reinterpret_cast<const float4*>(q);
            rd[0] = (w > 0) ? q[-1] : NEG;
            rd[1] = d4.x; rd[2] = d4.y; rd[3] = d4.z; rd[4] = d4.w;
            rd[5] = (w + 4 < WW) ? q[4] : NEG;
        } else {
            #pragma unroll
            for (int j = 0; j < 6; j++) rd[j] = NEG;
        }

        #pragma unroll
        for (int j = 0; j < 4; j++) {
            float v = rc[j + 1];
            float m = fmaxf(rc[j], rc[j + 2]);
            m = fmaxf(m, fmaxf(fmaxf(ru[j], ru[j + 1]), ru[j + 2]));
            m = fmaxf(m, fmaxf(fmaxf(rd[j], rd[j + 1]), rd[j + 2]));
            if (v >= m) {                          // keep iff no neighbor > v
                unsigned int ord = ordkey(v);
                atomicAdd(&g_zero[(b * NSH + sh) * NBUCK + (int)(ord >> 19)], 1);
                unsigned int idx = (unsigned int)(base + j);   // c*HW + hw
                mykeys[myn++] = ((unsigned long long)ord << 32) |
                                (unsigned long long)(~idx);
            }
        }
    }

    int local = 0;
    if (myn) local = atomicAdd(&s_cnt, myn);
    __syncthreads();
    if (threadIdx.x == 0) s_base = atomicAdd(&g_zero[SCOUNT_OFF + blockIdx.y], s_cnt);
    __syncthreads();
    if (myn) {
        int pos = s_base + local;
        for (int j = 0; j < myn; j++) {
            int pp = pos + j;
            if (pp < SURVCAP) g_surv[b * SURVCAP + pp] = mykeys[j];
        }
    }
}

// ---------------------------------------------------------------------------
// K2: per-batch threshold bucket (smallest T s.t. suffix count >= K)
// ---------------------------------------------------------------------------
__global__ void k2_thresh(int K) {
    int b = blockIdx.x;
    __shared__ int chunk[256];
    __shared__ int merged[NBUCK];       // 32 KB: shard-summed histogram
    int t = threadIdx.x;                // 256 threads, 32 buckets each
    int s = 0;
    #pragma unroll 1
    for (int j = 0; j < 32; j++) {
        int bk = t * 32 + j;
        int v = 0;
        #pragma unroll
        for (int sh = 0; sh < NSH; sh++)
            v += g_zero[(b * NSH + sh) * NBUCK + bk];
        merged[bk] = v;
        s += v;
    }
    chunk[t] = s;
    __syncthreads();

    if (t == 0) {
        int cum = 0;
        int T = 0;
        bool done = false;
        for (int cix = 255; cix >= 0 && !done; cix--) {
            if (cum + chunk[cix] >= K) {
                for (int j = 31; j >= 0; j--) {
                    cum += merged[cix * 32 + j];
                    if (cum >= K) { T = cix * 32 + j; done = true; break; }
                }
            } else {
                cum += chunk[cix];
            }
        }
        g_thresh[b] = T;   // collect criterion: bucket >= T  (0 if < K total)
    }
}

// ---------------------------------------------------------------------------
// K3: filter survivor list by threshold bucket into candidate arrays
// ---------------------------------------------------------------------------
__global__ void k3_collect() {
    int b = blockIdx.y;
    int i = blockIdx.x * blockDim.x + threadIdx.x;
    int n = g_zero[SCOUNT_OFF + b];
    if (n > SURVCAP) n = SURVCAP;
    if (i >= n) return;

    unsigned long long key = g_surv[b * SURVCAP + i];
    int bucket = (int)(key >> (32 + 19));
    if (bucket < g_thresh[b]) return;

    int pos = atomicAdd(&g_zero[COUNT_OFF + b], 1);
    if (pos < CAP) g_cand[b * CAP + pos] = key;
}

// ---------------------------------------------------------------------------
// K4: per-batch bitonic sort (desc, next_pow2(n) elems) + gather + write
// ---------------------------------------------------------------------------
__global__ __launch_bounds__(1024)
void k4_sort_gather(const float* __restrict__ cen_offset,
                    const float* __restrict__ direction,
                    const float* __restrict__ z_coor,
                    const float* __restrict__ dimf,
                    float* __restrict__ out,
                    int K) {
    __shared__ unsigned long long keys[CAP];   // 32 KB
    int b   = blockIdx.x;
    int tid = threadIdx.x;
    int n   = g_zero[COUNT_OFF + b];
    if (n > CAP) n = CAP;
    int m = 512;
    while (m < n) m <<= 1;                     // sort size, <= CAP

    for (int i = tid; i < m; i += blockDim.x)
        keys[i] = (i < n) ? g_cand[b * CAP + i] : 0ULL;
    __syncthreads();

    // Bitonic sort, descending
    for (int k2 = 2; k2 <= m; k2 <<= 1) {
        for (int j = k2 >> 1; j > 0; j >>= 1) {
            for (int i = tid; i < m; i += blockDim.x) {
                int ixj = i ^ j;
                if (ixj > i) {
                    unsigned long long a = keys[i];
                    unsigned long long c = keys[ixj];
                    bool up = ((i & k2) == 0);
                    if (up ? (a < c) : (a > c)) {
                        keys[i]   = c;
                        keys[ixj] = a;
                    }
                }
            }
            __syncthreads();
        }
    }

    for (int k = tid; k < K; k += blockDim.x) {
        float* o = out + ((size_t)b * K + k) * 10;
        unsigned long long key = keys[k];
        if (key == 0ULL) {
            #pragma unroll
            for (int q = 0; q < 10; q++) o[q] = 0.0f;
            continue;
        }
        unsigned int ord  = (unsigned int)(key >> 32);
        unsigned int bits = (ord & 0x80000000u) ? (ord ^ 0x80000000u) : ~ord;
        float score = sigclip(__uint_as_float(bits));
        unsigned int idx = ~((unsigned int)key);       // c*HW + hw
        int c  = (int)(idx / HWSZ);
        int hw = (int)(idx - (unsigned int)c * HWSZ);
        int r  = hw / WW;
        int w  = hw - r * WW;

        const float* off = cen_offset + (size_t)b * 2 * HWSZ;
        const float* dir = direction  + (size_t)b * 2 * HWSZ;
        const float* zc  = z_coor     + (size_t)b * 1 * HWSZ;
        const float* dm  = dimf       + (size_t)b * 3 * HWSZ;

        o[0] = score;
        o[1] = (float)w + sigclip(off[hw]);
        o[2] = (float)r + sigclip(off[HWSZ + hw]);
        o[3] = zc[hw];
        o[4] = dm[hw];
        o[5] = dm[HWSZ + hw];
        o[6] = dm[2 * HWSZ + hw];
        o[7] = dir[hw];
        o[8] = dir[HWSZ + hw];
        o[9] = (float)c;
    }
}

// ---------------------------------------------------------------------------
// Host launcher
// ---------------------------------------------------------------------------
extern "C" void kernel_launch(void* const* d_in, const int* in_sizes, int n_in,
                              void* d_out, int out_size) {
    const float* hm   = (const float*)d_in[0];
    const float* off  = (const float*)d_in[1];
    const float* dir  = (const float*)d_in[2];
    const float* zc   = (const float*)d_in[3];
    const float* dm   = (const float*)d_in[4];
    float* out = (float*)d_out;

    int B = in_sizes[0] / PLANE;
    if (B < 1) B = 1;
    if (B > MAXB) B = MAXB;
    int K = out_size / (B * 10);
    if (K < 1) K = 1;

    void* zptr = nullptr;
    cudaGetSymbolAddress(&zptr, g_zero);
    cudaMemsetAsync(zptr, 0, ZERO_INTS * sizeof(int), 0);

    k1_nms<<<dim3(K1_BLOCKS, B), 256>>>(hm);
    k2_thresh<<<B, 256>>>(K);
    k3_collect<<<dim3(SURVCAP / 256, B), 256>>>();
    k4_sort_gather<<<B, 1024>>>(off, dir, zc, dm, out, K);
}

// round 5
// speedup vs baseline: 2.8034x; 1.0462x over previous
#include <cuda_runtime.h>
#include <cstdint>

// Problem geometry (fixed for this dataset instance)
#define CC    3
#define HH    496
#define WW    432
#define HWSZ  (HH * WW)            // 214272
#define PLANE (CC * HWSZ)          // 642816
#define MAXB  8
#define NBUCK 8192                 // ordered_bits >> 19
#define NSH   4                    // histogram shards (contention relief)
#define CAP   4096                 // candidate buffer per batch
#define SURVCAP 131072             // survivor buffer per batch (expect ~72K)
#define K1_BLOCKS ((PLANE + 1023) / 1024)   // 628 blocks of 256 thr x 4 px

// One contiguous zeroed scratch region: hist[b][sh][bucket] then counters.
#define HIST_INTS   (MAXB * NSH * NBUCK)       // 262144 ints = 1 MB
#define SCOUNT_OFF  (HIST_INTS)                // 8 ints
#define COUNT_OFF   (HIST_INTS + MAXB)         // 8 ints
#define ZERO_INTS   (HIST_INTS + 2 * MAXB)

__device__ int                g_zero[ZERO_INTS];
__device__ int                g_thresh[MAXB];
__device__ unsigned long long g_surv[MAXB * SURVCAP];   // 8 MB
__device__ unsigned long long g_cand[MAXB * CAP];

__device__ __forceinline__ float sigclip(float x) {
    float s = 1.0f / (1.0f + __expf(-x));
    return fminf(fmaxf(s, 1.0e-4f), 1.0f - 1.0e-4f);
}

// total-order key for floats (monotone map to uint32, ascending)
__device__ __forceinline__ unsigned int ordkey(float v) {
    unsigned int bits = __float_as_uint(v);
    return bits ^ ((unsigned int)((int)bits >> 31) | 0x80000000u);
}

// ---------------------------------------------------------------------------
// K1: raw-domain 3x3 NMS (sigmoid is monotone) -> survivor list + sharded hist
// ---------------------------------------------------------------------------
__global__ __launch_bounds__(256)
void k1_nms(const float* __restrict__ hm) {
    int b    = blockIdx.y;
    int base = blockIdx.x * 1024 + threadIdx.x * 4;   // within plane
    int sh   = threadIdx.x & (NSH - 1);

    __shared__ int s_cnt, s_base;
    if (threadIdx.x == 0) s_cnt = 0;
    __syncthreads();

    unsigned long long mykeys[4];
    int myn = 0;

    if (base < PLANE) {
        const float* plane = hm + (size_t)b * PLANE;
        int hw = base % HWSZ;
        int h  = hw / WW;
        int w  = hw % WW;
        const float* p = plane + base;
        const float NEG = -3.4e38f;

        float rc[6], ru[6], rd[6];
        float4 c4 = *reinterpret_cast<const float4*>(p);
        rc[0] = (w > 0)        ? p[-1] : NEG;
        rc[1] = c4.x; rc[2] = c4.y; rc[3] = c4.z; rc[4] = c4.w;
        rc[5] = (w + 4 < WW)   ? p[4]  : NEG;

        if (h > 0) {
            const float* q = p - WW;
            float4 u4 = *reinterpret_cast<const float4*>(q);
            ru[0] = (w > 0) ? q[-1] : NEG;
            ru[1] = u4.x; ru[2] = u4.y; ru[3] = u4.z; ru[4] = u4.w;
            ru[5] = (w + 4 < WW) ? q[4] : NEG;
        } else {
            #pragma unroll
            for (int j = 0; j < 6; j++) ru[j] = NEG;
        }
        if (h + 1 < HH) {
            const float* q = p + WW;
            float4 d4 = *reinterpret_cast<const float4*>(q);
            rd[0] = (w > 0) ? q[-1] : NEG;
            rd[1] = d4.x; rd[2] = d4.y; rd[3] = d4.z; rd[4] = d4.w;
            rd[5] = (w + 4 < WW) ? q[4] : NEG;
        } else {
            #pragma unroll
            for (int j = 0; j < 6; j++) rd[j] = NEG;
        }

        #pragma unroll
        for (int j = 0; j < 4; j++) {
            float v = rc[j + 1];
            float m = fmaxf(rc[j], rc[j + 2]);
            m = fmaxf(m, fmaxf(fmaxf(ru[j], ru[j + 1]), ru[j + 2]));
            m = fmaxf(m, fmaxf(fmaxf(rd[j], rd[j + 1]), rd[j + 2]));
            if (v >= m) {                          // keep iff no neighbor > v
                unsigned int ord = ordkey(v);
                atomicAdd(&g_zero[(b * NSH + sh) * NBUCK + (int)(ord >> 19)], 1);
                unsigned int idx = (unsigned int)(base + j);   // c*HW + hw
                mykeys[myn++] = ((unsigned long long)ord << 32) |
                                (unsigned long long)(~idx);
            }
        }
    }

    int local = 0;
    if (myn) local = atomicAdd(&s_cnt, myn);
    __syncthreads();
    if (threadIdx.x == 0) s_base = atomicAdd(&g_zero[SCOUNT_OFF + blockIdx.y], s_cnt);
    __syncthreads();
    if (myn) {
        int pos = s_base + local;
        for (int j = 0; j < myn; j++) {
            int pp = pos + j;
            if (pp < SURVCAP) g_surv[b * SURVCAP + pp] = mykeys[j];
        }
    }
}

// ---------------------------------------------------------------------------
// K2: per-batch threshold bucket (smallest T s.t. suffix count >= K)
// ---------------------------------------------------------------------------
__global__ void k2_thresh(int K) {
    int b = blockIdx.x;
    __shared__ int chunk[256];
    __shared__ int merged[NBUCK];       // 32 KB: shard-summed histogram
    int t = threadIdx.x;                // 256 threads, 32 buckets each
    int s = 0;
    #pragma unroll 1
    for (int j = 0; j < 32; j++) {
        int bk = t * 32 + j;
        int v = 0;
        #pragma unroll
        for (int sh = 0; sh < NSH; sh++)
            v += g_zero[(b * NSH + sh) * NBUCK + bk];
        merged[bk] = v;
        s += v;
    }
    chunk[t] = s;
    __syncthreads();

    if (t == 0) {
        int cum = 0;
        int T = 0;
        bool done = false;
        for (int cix = 255; cix >= 0 && !done; cix--) {
            if (cum + chunk[cix] >= K) {
                for (int j = 31; j >= 0; j--) {
                    cum += merged[cix * 32 + j];
                    if (cum >= K) { T = cix * 32 + j; done = true; break; }
                }
            } else {
                cum += chunk[cix];
            }
        }
        g_thresh[b] = T;   // collect criterion: bucket >= T  (0 if < K total)
    }
}

// ---------------------------------------------------------------------------
// K3: filter survivor list by threshold bucket into candidate arrays
//     4 consecutive keys per thread (two ulonglong2 loads)
// ---------------------------------------------------------------------------
__global__ __launch_bounds__(256)
void k3_collect() {
    int b    = blockIdx.y;
    int base = (blockIdx.x * 256 + threadIdx.x) * 4;
    int n = g_zero[SCOUNT_OFF + b];
    if (n > SURVCAP) n = SURVCAP;
    if (base >= n) return;
    int T = g_thresh[b];

    const ulonglong2* sp =
        reinterpret_cast<const ulonglong2*>(&g_surv[b * SURVCAP + base]);
    ulonglong2 v0 = sp[0];
    ulonglong2 v1 = sp[1];
    unsigned long long kk[4] = { v0.x, v0.y, v1.x, v1.y };

    #pragma unroll
    for (int j = 0; j < 4; j++) {
        if (base + j >= n) break;
        unsigned long long key = kk[j];
        if ((int)(key >> 51) >= T) {
            int pos = atomicAdd(&g_zero[COUNT_OFF + b], 1);
            if (pos < CAP) g_cand[b * CAP + pos] = key;
        }
    }
}

// ---------------------------------------------------------------------------
// K4: per-batch rank selection (no sort) + gather + write detections.
//     Keys are unique -> rank(key) = #{j: keys[j] > key} is a bijection.
// ---------------------------------------------------------------------------
__global__ __launch_bounds__(1024)
void k4_rank_gather(const float* __restrict__ cen_offset,
                    const float* __restrict__ direction,
                    const float* __restrict__ z_coor,
                    const float* __restrict__ dimf,
                    float* __restrict__ out,
                    int K) {
    __shared__ unsigned long long keys[CAP];   // 32 KB
    int b   = blockIdx.x;
    int tid = threadIdx.x;
    int n   = g_zero[COUNT_OFF + b];
    if (n > CAP) n = CAP;

    for (int i = tid; i < n; i += 1024)
        keys[i] = g_cand[b * CAP + i];
    __syncthreads();

    // zero-fill rows beyond the number of candidates
    for (int k = n + tid; k < K; k += 1024) {
        float* o = out + ((size_t)b * K + k) * 10;
        #pragma unroll
        for (int q = 0; q < 10; q++) o[q] = 0.0f;
    }

    const float* off = cen_offset + (size_t)b * 2 * HWSZ;
    const float* dir = direction  + (size_t)b * 2 * HWSZ;
    const float* zc  = z_coor     + (size_t)b * 1 * HWSZ;
    const float* dm  = dimf       + (size_t)b * 3 * HWSZ;

    for (int t = tid; t < n; t += 1024) {
        unsigned long long key = keys[t];
        int rank = 0;
        int j = 0;
        for (; j + 4 <= n; j += 4) {
            rank += (keys[j]     > key);
            rank += (keys[j + 1] > key);
            rank += (keys[j + 2] > key);
            rank += (keys[j + 3] > key);
        }
        for (; j < n; j++) rank += (keys[j] > key);
        if (rank >= K) continue;

        unsigned int ord  = (unsigned int)(key >> 32);
        unsigned int bits = (ord & 0x80000000u) ? (ord ^ 0x80000000u) : ~ord;
        float score = sigclip(__uint_as_float(bits));
        unsigned int idx = ~((unsigned int)key);       // c*HW + hw
        int c  = (int)(idx / HWSZ);
        int hw = (int)(idx - (unsigned int)c * HWSZ);
        int r  = hw / WW;
        int w  = hw - r * WW;

        float* o = out + ((size_t)b * K + rank) * 10;
        o[0] = score;
        o[1] = (float)w + sigclip(off[hw]);
        o[2] = (float)r + sigclip(off[HWSZ + hw]);
        o[3] = zc[hw];
        o[4] = dm[hw];
        o[5] = dm[HWSZ + hw];
        o[6] = dm[2 * HWSZ + hw];
        o[7] = dir[hw];
        o[8] = dir[HWSZ + hw];
        o[9] = (float)c;
    }
}

// ---------------------------------------------------------------------------
// Host launcher
// ---------------------------------------------------------------------------
extern "C" void kernel_launch(void* const* d_in, const int* in_sizes, int n_in,
                              void* d_out, int out_size) {
    const float* hm   = (const float*)d_in[0];
    const float* off  = (const float*)d_in[1];
    const float* dir  = (const float*)d_in[2];
    const float* zc   = (const float*)d_in[3];
    const float* dm   = (const float*)d_in[4];
    float* out = (float*)d_out;

    int B = in_sizes[0] / PLANE;
    if (B < 1) B = 1;
    if (B > MAXB) B = MAXB;
    int K = out_size / (B * 10);
    if (K < 1) K = 1;

    void* zptr = nullptr;
    cudaGetSymbolAddress(&zptr, g_zero);
    cudaMemsetAsync(zptr, 0, ZERO_INTS * sizeof(int), 0);

    k1_nms<<<dim3(K1_BLOCKS, B), 256>>>(hm);
    k2_thresh<<<B, 256>>>(K);
    k3_collect<<<dim3(SURVCAP / 1024, B), 256>>>();
    k4_rank_gather<<<B, 1024>>>(off, dir, zc, dm, out, K);
}